// round 15
// baseline (speedup 1.0000x reference)
#include <cuda_runtime.h>
#include <cuda_bf16.h>
#include <math.h>
#include <stdint.h>

// ---------------------------------------------------------------------------
// QuantumTSTransformer: 12-qubit statevector sim, packed f32x2 arithmetic.
//   B=64, T=32, DEGREE=4, sim14 2 layers (96 rots), qff layer (48), DIM=4096.
// R14: 2 kernels.
//   prep: zero g_work[1..4] + queue reset (512 blocks).
//   circuit_fused: persistent (592 CTAs, 4/SM), ticket queue over 8192
//     circuit items (d,b,t) PLUS 64 final items (one per b, overlapping the
//     circuit tail). red.release / ld.acquire done-counters. d=0 items
//     compute their own rotation params and start from analytic |0..0>.
//     Final items: assemble poly acc (analytic p[0]), normalize, qff layer,
//     Pauli expvals, output linear.
// ---------------------------------------------------------------------------

#define NQ       12
#define DIM      4096
#define BATCH    64
#define TSTEPS   32
#define NROTS    96
#define QFFROTS  48
#define DEGREE   4
#define FDIM     64
#define ODIM     8
#define CIRC_ITEMS (DEGREE * BATCH * TSTEPS)    // 8192
#define NITEMS   (CIRC_ITEMS + BATCH)           // 8256 (incl. final items)
#define NPERS    592                            // 4 CTAs x 148 SMs
#define CIRC_SMEM (DIM * 8 + 1024)              // st + coeffs/final scratch

typedef unsigned long long ull;

// Scratch (device globals: no allocation allowed)
__device__ float2 g_work[DEGREE + 1][BATCH * DIM];   // [0] unused (analytic)
__device__ float2 g_cs[BATCH * TSTEPS * NROTS];      // (cos(h), sin(h)) per rot
__device__ unsigned g_ticket;                        // work queue head
__device__ unsigned g_done[DEGREE * BATCH];          // flat: slot = d*64+b

// ---------------- packed f32x2 helpers ----------------
__device__ __forceinline__ ull pk2(float x, float y) {
    ull r; asm("mov.b64 %0, {%1, %2};" : "=l"(r) : "f"(x), "f"(y)); return r;
}
__device__ __forceinline__ ull dup2(float x) { return pk2(x, x); }
__device__ __forceinline__ float2 upk(ull v) {
    float2 r; asm("mov.b64 {%0, %1}, %2;" : "=f"(r.x), "=f"(r.y) : "l"(v)); return r;
}
__device__ __forceinline__ ull swp(ull v) {   // (x,y) -> (y,x)
    ull r;
    asm("{\n\t.reg .b32 lo, hi;\n\tmov.b64 {lo, hi}, %1;\n\tmov.b64 %0, {hi, lo};\n\t}"
        : "=l"(r) : "l"(v));
    return r;
}
__device__ __forceinline__ ull f2mul(ull a, ull b) {
    ull r; asm("mul.rn.f32x2 %0, %1, %2;" : "=l"(r) : "l"(a), "l"(b)); return r;
}
__device__ __forceinline__ ull f2fma(ull a, ull b, ull c) {
    ull r; asm("fma.rn.f32x2 %0, %1, %2, %3;" : "=l"(r) : "l"(a), "l"(b), "l"(c)); return r;
}
__device__ __forceinline__ void red2(float2* p, float2 v) {
    asm volatile("red.global.add.v2.f32 [%0], {%1, %2};"
                 :: "l"(p), "f"(v.x), "f"(v.y) : "memory");
}

// smem slot swizzle: bijective, conflict-free for all phase patterns
__device__ __forceinline__ uint32_t sw(uint32_t i) { return i ^ ((i >> 4) & 0xFu); }

// base address: deposit 8 tid bits into the amplitude-index bits NOT in {P0..P3}
template<int P0, int P1, int P2, int P3>
__device__ __forceinline__ uint32_t phase_base(int tid) {
    constexpr uint32_t M = (1u << P0) | (1u << P1) | (1u << P2) | (1u << P3);
    uint32_t base = 0;
    int tb = 0;
#pragma unroll
    for (int pos = 0; pos < NQ; ++pos) {
        if (!((M >> pos) & 1u)) {
            base |= ((uint32_t)(tid >> tb) & 1u) << pos;
            ++tb;
        }
    }
    return base;
}

template<int P0, int P1, int P2, int P3>
__device__ __forceinline__ uint32_t pidx(uint32_t base, int j) {
    return base
        | ((j & 1) ? (1u << P0) : 0u)
        | ((j & 2) ? (1u << P1) : 0u)
        | ((j & 4) ? (1u << P2) : 0u)
        | ((j & 8) ? (1u << P3) : 0u);
}

// RY on register-bit RB:  a0' = c a0 - s a1 ; a1' = s a0 + c a1  (componentwise)
template<int RB>
__device__ __forceinline__ void gry(ull* r, float2 cs) {
    const ull c2 = dup2(cs.x), s2 = dup2(cs.y), ns2 = dup2(-cs.y);
#pragma unroll
    for (int j = 0; j < 16; ++j) {
        if (!(j & (1 << RB))) {
            ull a0 = r[j], a1 = r[j | (1 << RB)];
            r[j]            = f2fma(c2, a0, f2mul(ns2, a1));
            r[j | (1 << RB)] = f2fma(s2, a0, f2mul(c2, a1));
        }
    }
}

// CRX: control RBC==1, target RBT.  a0' = c a0 - i s a1 ; a1' = c a1 - i s a0.
template<int RBC, int RBT>
__device__ __forceinline__ void gcrx(ull* r, float2 cs) {
    const ull c2 = dup2(cs.x);
    const ull spm = pk2(cs.y, -cs.y);
#pragma unroll
    for (int j = 0; j < 16; ++j) {
        if ((j & (1 << RBC)) && !(j & (1 << RBT))) {
            ull a0 = r[j], a1 = r[j | (1 << RBT)];
            r[j]             = f2fma(c2, a0, f2mul(spm, swp(a1)));
            r[j | (1 << RBT)] = f2fma(c2, a1, f2mul(spm, swp(a0)));
        }
    }
}

#define PHASE_LOAD(P0,P1,P2,P3)                                            \
    uint32_t base = phase_base<P0,P1,P2,P3>(tid);                          \
    ull r[16];                                                             \
    _Pragma("unroll")                                                      \
    for (int j = 0; j < 16; ++j) r[j] = st[sw(pidx<P0,P1,P2,P3>(base, j))];

#define PHASE_STORE(P0,P1,P2,P3)                                           \
    _Pragma("unroll")                                                      \
    for (int j = 0; j < 16; ++j) st[sw(pidx<P0,P1,P2,P3>(base, j))] = r[j];

// ---- the 8 phases of one sim14 layer (wire w <-> amplitude bit 11-w) ----

__device__ __forceinline__ void phA1_body(ull* r, const float2* c) {
    gry<0>(r, c[0]);  gry<1>(r, c[11]); gry<2>(r, c[10]); gry<3>(r, c[9]);
    gcrx<1, 0>(r, c[12]); gcrx<2, 1>(r, c[13]); gcrx<3, 2>(r, c[14]);
}
__device__ __forceinline__ void phA1(ull* st, const float2* c, int tid) {
    PHASE_LOAD(11, 0, 1, 2);
    phA1_body(r, c);
    PHASE_STORE(11, 0, 1, 2);
}
// phA1 starting from the analytic |0..0> state (d=0 items): no load phase.
__device__ __forceinline__ void phA1_zero(ull* st, const float2* c, int tid) {
    uint32_t base = phase_base<11, 0, 1, 2>(tid);
    ull r[16];
#pragma unroll
    for (int j = 0; j < 16; ++j) r[j] = 0ull;
    if (tid == 0) r[0] = pk2(1.f, 0.f);
    phA1_body(r, c);
    PHASE_STORE(11, 0, 1, 2);
}
__device__ __forceinline__ void phA2(ull* st, const float2* c, int tid) {
    PHASE_LOAD(2, 3, 4, 5);
    gry<1>(r, c[8]); gry<2>(r, c[7]); gry<3>(r, c[6]);
    gcrx<1, 0>(r, c[15]); gcrx<2, 1>(r, c[16]); gcrx<3, 2>(r, c[17]);
    PHASE_STORE(2, 3, 4, 5);
}
__device__ __forceinline__ void phA3(ull* st, const float2* c, int tid) {
    PHASE_LOAD(5, 6, 7, 8);
    gry<1>(r, c[5]); gry<2>(r, c[4]); gry<3>(r, c[3]);
    gcrx<1, 0>(r, c[18]); gcrx<2, 1>(r, c[19]); gcrx<3, 2>(r, c[20]);
    PHASE_STORE(5, 6, 7, 8);
}
__device__ __forceinline__ void phA4(ull* st, const float2* c, int tid) {
    PHASE_LOAD(8, 9, 10, 11);
    gry<1>(r, c[2]); gry<2>(r, c[1]);
    gcrx<1, 0>(r, c[21]); gcrx<2, 1>(r, c[22]); gcrx<3, 2>(r, c[23]);
    PHASE_STORE(8, 9, 10, 11);
}
__device__ __forceinline__ void phB1(ull* st, const float2* c, int tid) {
    PHASE_LOAD(1, 0, 11, 10);
    gry<0>(r, c[34]); gry<1>(r, c[35]); gry<2>(r, c[24]); gry<3>(r, c[25]);
    gcrx<1, 0>(r, c[36]); gcrx<2, 1>(r, c[37]); gcrx<3, 2>(r, c[38]);
    PHASE_STORE(1, 0, 11, 10);
}
__device__ __forceinline__ void phB2(ull* st, const float2* c, int tid) {
    PHASE_LOAD(10, 9, 8, 7);
    gry<1>(r, c[26]); gry<2>(r, c[27]); gry<3>(r, c[28]);
    gcrx<1, 0>(r, c[39]); gcrx<2, 1>(r, c[40]); gcrx<3, 2>(r, c[41]);
    PHASE_STORE(10, 9, 8, 7);
}
__device__ __forceinline__ void phB3(ull* st, const float2* c, int tid) {
    PHASE_LOAD(7, 6, 5, 4);
    gry<1>(r, c[29]); gry<2>(r, c[30]); gry<3>(r, c[31]);
    gcrx<1, 0>(r, c[42]); gcrx<2, 1>(r, c[43]); gcrx<3, 2>(r, c[44]);
    PHASE_STORE(7, 6, 5, 4);
}
__device__ __forceinline__ void phB4(ull* st, const float2* c, int tid) {
    PHASE_LOAD(4, 3, 2, 1);
    gry<1>(r, c[32]); gry<2>(r, c[33]);
    gcrx<1, 0>(r, c[45]); gcrx<2, 1>(r, c[46]); gcrx<3, 2>(r, c[47]);
    PHASE_STORE(4, 3, 2, 1);
}

__device__ __forceinline__ void run_layer(ull* st, const float2* c, int tid) {
    phA1(st, c, tid); __syncthreads();
    phA2(st, c, tid); __syncthreads();
    phA3(st, c, tid); __syncthreads();
    phA4(st, c, tid); __syncthreads();
    phB1(st, c, tid); __syncthreads();
    phB2(st, c, tid); __syncthreads();
    phB3(st, c, tid); __syncthreads();
    phB4(st, c, tid); __syncthreads();
}

// ---------------------------------------------------------------------------
// Kernel 1: prep = zero g_work[1..4] (+ queue reset in block 0).
// ---------------------------------------------------------------------------
#define INIT_BLKS 512
__global__ void prep_kernel() {
    if (blockIdx.x == 0) {
        if (threadIdx.x == 0) g_ticket = 0u;
        if (threadIdx.x < DEGREE * BATCH) g_done[threadIdx.x] = 0u;
    }
    uint32_t tgid = blockIdx.x * 256 + threadIdx.x;     // 0..131071
    float4* p = (float4*)&g_work[0][0] + 131072 + (size_t)tgid * 4;
    float4 z = make_float4(0.f, 0.f, 0.f, 0.f);
    p[0] = z; p[1] = z; p[2] = z; p[3] = z;
}

// ---------------------------------------------------------------------------
// Kernel 2: persistent fused circuits + finals. 592 CTAs, ticket queue.
// Items [0, 8192): circuits (d,b,t). Items [8192, 8256): final per b.
// ---------------------------------------------------------------------------
__global__ void __launch_bounds__(256, 4)
circuit_fused(const float* __restrict__ x,
              const float* __restrict__ Wp,
              const float* __restrict__ bp,
              const float* __restrict__ mix_re,
              const float* __restrict__ mix_im,
              const float* __restrict__ poly,
              const float* __restrict__ qff,
              const float* __restrict__ W_out,
              const float* __restrict__ b_out,
              float* __restrict__ out) {
    extern __shared__ ull dsm[];
    ull* st = dsm;                            // DIM
    float2* cc = (float2*)(dsm + DIM);        // 96 coeffs + mix at [96]
    __shared__ unsigned s_ticket;

    const int tid = threadIdx.x;
    unsigned prev_slot = 0xFFFFFFFFu;         // no completed item yet

    for (;;) {
        __syncthreads();                      // all threads done with prev item
        if (tid == 0) {
            if (prev_slot != 0xFFFFFFFFu)
                asm volatile("red.release.gpu.global.add.u32 [%0], 1;"
                             :: "l"(&g_done[prev_slot]) : "memory");
            s_ticket = atomicAdd(&g_ticket, 1u);
        }
        __syncthreads();
        const unsigned item = s_ticket;
        if (item >= NITEMS) break;
        prev_slot = 0xFFFFFFFFu;

        if (item >= CIRC_ITEMS) {
            // ================= FINAL item for batch b =================
            const int b = item - CIRC_ITEMS;
            // wait for all 32 producers of work[DEGREE] for this b
            if (tid == 0) {
                unsigned v;
                for (;;) {
                    asm volatile("ld.acquire.gpu.global.u32 %0, [%1];"
                                 : "=r"(v) : "l"(&g_done[(DEGREE - 1) * 64 + b]) : "memory");
                    if (v >= (unsigned)TSTEPS) break;
                    __nanosleep(64);
                }
            }
            __syncthreads();

            float* red_s = (float*)(dsm + DIM);        // 37 floats
            float2* csqff = (float2*)(red_s + 40);     // 48 float2

            if (tid < QFFROTS) {
                float hq = 0.5f * qff[tid];
                float sq, cq; __sincosf(hq, &sq, &cq);
                csqff[tid] = make_float2(cq, sq);
            }
            float p[DEGREE + 1];
#pragma unroll
            for (int d = 0; d <= DEGREE; ++d) p[d] = poly[d];
            float sabs = 0.f;
#pragma unroll
            for (int d = 0; d <= DEGREE; ++d) sabs += fabsf(p[d]);
            const float inv_s = 1.f / sabs;

            if (tid == 0) red_s[36] = 0.f;
            const ull* wflat = (const ull*)&g_work[0][0];
            float lsq = 0.f;
#pragma unroll
            for (int k = 0; k < 16; ++k) {
                int i = tid + 256 * k;
                ull v = 0ull;
#pragma unroll
                for (int d = 1; d <= DEGREE; ++d) {
                    ull w = wflat[(size_t)d * (BATCH * DIM) + b * DIM + i];
                    v = f2fma(dup2(p[d]), w, v);
                }
                if (i == 0) v = f2fma(dup2(p[0]), pk2(1.f, 0.f), v);
                v = f2mul(dup2(inv_s), v);
                st[sw((uint32_t)i)] = v;
                float2 vf = upk(v);
                lsq += vf.x * vf.x + vf.y * vf.y;
            }
#pragma unroll
            for (int o = 16; o > 0; o >>= 1) lsq += __shfl_xor_sync(0xffffffffu, lsq, o);
            if ((tid & 31) == 0) atomicAdd(&red_s[36], lsq);
            __syncthreads();

            const float f = 1.f / (sqrtf(red_s[36]) + 1e-9f);
            const ull f2 = dup2(f);
#pragma unroll
            for (int k = 0; k < 16; ++k) {
                int i = tid + 256 * k;
                uint32_t s_ = sw((uint32_t)i);
                st[s_] = f2mul(f2, st[s_]);
            }
            __syncthreads();

            run_layer(st, csqff, tid);        // qff: one sim14 layer

            if (tid < 36) red_s[tid] = 0.f;
            __syncthreads();

            float xx[NQ], yy[NQ], zz[NQ];
#pragma unroll
            for (int w = 0; w < NQ; ++w) { xx[w] = 0.f; yy[w] = 0.f; zz[w] = 0.f; }
#pragma unroll
            for (int k = 0; k < 16; ++k) {
                int i = tid + 256 * k;
                float2 a = upk(st[sw((uint32_t)i)]);
                float n2 = a.x * a.x + a.y * a.y;
#pragma unroll
                for (int w = 0; w < NQ; ++w) {
                    int pbit = 11 - w;
                    if (((i >> pbit) & 1) == 0) {
                        float2 a1 = upk(st[sw((uint32_t)(i | (1 << pbit)))]);
                        xx[w] += 2.f * (a.x * a1.x + a.y * a1.y);
                        yy[w] += 2.f * (a.x * a1.y - a.y * a1.x);
                        zz[w] += n2;
                    } else {
                        zz[w] -= n2;
                    }
                }
            }
#pragma unroll
            for (int w = 0; w < NQ; ++w) {
                atomicAdd(&red_s[w], xx[w]);
                atomicAdd(&red_s[12 + w], yy[w]);
                atomicAdd(&red_s[24 + w], zz[w]);
            }
            __syncthreads();

            if (tid < ODIM) {
                float acc = b_out[tid];
#pragma unroll
                for (int j = 0; j < 36; ++j) acc += W_out[tid * 36 + j] * red_s[j];
                out[b * ODIM + tid] = acc;
            }
            continue;                          // no signal for final items
        }

        // ================= CIRCUIT item (d,b,t) =================
        const unsigned slot = item >> 5;      // d*64 + b
        const int b = slot & 63;
        const int t = item & 31;
        const int d = slot >> 6;
        const int bt = b * TSTEPS + t;

        if (d == 0) {
            // compute this (b,t)'s rotation params in-item
            float4* xr = (float4*)st;         // reuse st head as x staging
            if (tid < FDIM / 4) xr[tid] = ((const float4*)(x + bt * FDIM))[tid];
            __syncthreads();
            if (tid < NROTS) {
                const float4* wrow = (const float4*)(Wp + tid * FDIM);
                float acc = bp[tid];
#pragma unroll
                for (int f = 0; f < FDIM / 4; ++f) {
                    float4 xv = xr[f], wv = wrow[f];
                    acc += xv.x * wv.x + xv.y * wv.y + xv.z * wv.z + xv.w * wv.w;
                }
                float sg = 1.0f / (1.0f + __expf(-acc));
                float h = 3.14159265358979323846f * sg;
                float sv, cv; __sincosf(h, &sv, &cv);
                float2 cs_ = make_float2(cv, sv);
                cc[tid] = cs_;
                g_cs[bt * NROTS + tid] = cs_;   // publish for d>0 consumers
            }
            if (tid == NROTS) cc[NROTS] = make_float2(mix_re[t], mix_im[t]);
            __syncthreads();
            phA1_zero(st, cc, tid); __syncthreads();   // analytic |0..0> start
        } else {
            // wait for the 32 producers of work[d] for this b
            if (tid == 0) {
                unsigned v;
                for (;;) {
                    asm volatile("ld.acquire.gpu.global.u32 %0, [%1];"
                                 : "=r"(v) : "l"(&g_done[slot - 64]) : "memory");
                    if (v >= (unsigned)TSTEPS) break;
                    __nanosleep(64);
                }
            }
            __syncthreads();                  // broadcast acquire to CTA

            const ull* win = (const ull*)&g_work[d][b * DIM];
#pragma unroll
            for (int k = 0; k < 16; ++k) {
                int i = tid + 256 * k;
                st[sw((uint32_t)i)] = win[i];
            }
            if (tid < NROTS) cc[tid] = g_cs[bt * NROTS + tid];
            if (tid == NROTS) cc[NROTS] = make_float2(mix_re[t], mix_im[t]);
            __syncthreads();
            phA1(st, cc, tid); __syncthreads();
        }

        // remaining 7 phases of layer 0
        phA2(st, cc, tid); __syncthreads();
        phA3(st, cc, tid); __syncthreads();
        phA4(st, cc, tid); __syncthreads();
        phB1(st, cc, tid); __syncthreads();
        phB2(st, cc, tid); __syncthreads();
        phB3(st, cc, tid); __syncthreads();
        phB4(st, cc, tid); __syncthreads();
        // layer 1: first 7 phases, last phase fused with mix+flush
        const float2* c1 = cc + 48;
        phA1(st, c1, tid); __syncthreads();
        phA2(st, c1, tid); __syncthreads();
        phA3(st, c1, tid); __syncthreads();
        phA4(st, c1, tid); __syncthreads();
        phB1(st, c1, tid); __syncthreads();
        phB2(st, c1, tid); __syncthreads();
        phB3(st, c1, tid); __syncthreads();
        {   // phB4 without store: mix[t] * psi -> red.global directly
            float2* wout = &g_work[d + 1][b * DIM];
            PHASE_LOAD(4, 3, 2, 1);
            gry<1>(r, c1[32]); gry<2>(r, c1[33]);
            gcrx<1, 0>(r, c1[45]); gcrx<2, 1>(r, c1[46]); gcrx<3, 2>(r, c1[47]);
            float2 mx = cc[NROTS];
            const ull mr2 = dup2(mx.x);
            const ull mpm = pk2(-mx.y, mx.y);
#pragma unroll
            for (int j = 0; j < 16; ++j) {
                uint32_t i = pidx<4, 3, 2, 1>(base, j);
                ull v = f2fma(mr2, r[j], f2mul(mpm, swp(r[j])));
                red2(&wout[i], upk(v));
            }
        }
        prev_slot = slot;                     // signal at next loop top
    }
}

// ---------------------------------------------------------------------------
// Inputs (metadata order): x, W_proj, b_proj, poly_coeffs, mix_re, mix_im,
//                          qff_params, W_out, b_out.  Output: float32 [64,8].
// ---------------------------------------------------------------------------
extern "C" void kernel_launch(void* const* d_in, const int* in_sizes, int n_in,
                              void* d_out, int out_size) {
    (void)in_sizes; (void)n_in; (void)out_size;
    const float* x      = (const float*)d_in[0];
    const float* W_proj = (const float*)d_in[1];
    const float* b_proj = (const float*)d_in[2];
    const float* poly   = (const float*)d_in[3];
    const float* mix_re = (const float*)d_in[4];
    const float* mix_im = (const float*)d_in[5];
    const float* qff    = (const float*)d_in[6];
    const float* W_out  = (const float*)d_in[7];
    const float* b_out  = (const float*)d_in[8];
    float* out = (float*)d_out;

    cudaFuncSetAttribute(circuit_fused,
                         cudaFuncAttributeMaxDynamicSharedMemorySize, CIRC_SMEM);

    prep_kernel<<<INIT_BLKS, 256>>>();
    circuit_fused<<<NPERS, 256, CIRC_SMEM>>>(x, W_proj, b_proj, mix_re, mix_im,
                                             poly, qff, W_out, b_out, out);
}

// round 16
// speedup vs baseline: 1.0021x; 1.0021x over previous
#include <cuda_runtime.h>
#include <cuda_bf16.h>
#include <math.h>
#include <stdint.h>

// ---------------------------------------------------------------------------
// QuantumTSTransformer: 12-qubit statevector sim, packed f32x2 arithmetic.
//   B=64, T=32, DEGREE=4, sim14 2 layers (96 rots), qff layer (48), DIM=4096.
// R15 (= R13 + warp-local runs): 3 kernels.
//   prep: zero g_work[1..4] + queue reset.
//   circuit_fused: persistent (592 CTAs, 4/SM), ticket queue over 8192
//     (d,b,t) items, red.release/ld.acquire done counters. Phases paired into
//     runs sharing fixed warp-bit positions F so intra-run phase boundaries
//     need only __syncwarp (each warp reads exactly what it wrote). sw5 fold
//     swizzle + per-phase deposits keep all LDS/STS conflict-free.
//   final: analytic p[0], assemble, normalize, qff, expvals, linear.
// ---------------------------------------------------------------------------

#define NQ       12
#define DIM      4096
#define BATCH    64
#define TSTEPS   32
#define NROTS    96
#define QFFROTS  48
#define DEGREE   4
#define FDIM     64
#define ODIM     8
#define NITEMS   (DEGREE * BATCH * TSTEPS)      // 8192
#define NPERS    592                            // 4 CTAs x 148 SMs
#define CIRC_SMEM (DIM * 8 + 1024)              // st + coeffs

typedef unsigned long long ull;

// Scratch (device globals: no allocation allowed)
__device__ float2 g_work[DEGREE + 1][BATCH * DIM];   // [0] unused (analytic)
__device__ float2 g_cs[BATCH * TSTEPS * NROTS];      // (cos(h), sin(h)) per rot
__device__ unsigned g_ticket;                        // work queue head
__device__ unsigned g_done[DEGREE * BATCH];          // flat: slot = d*64+b

// ---------------- packed f32x2 helpers ----------------
__device__ __forceinline__ ull pk2(float x, float y) {
    ull r; asm("mov.b64 %0, {%1, %2};" : "=l"(r) : "f"(x), "f"(y)); return r;
}
__device__ __forceinline__ ull dup2(float x) { return pk2(x, x); }
__device__ __forceinline__ float2 upk(ull v) {
    float2 r; asm("mov.b64 {%0, %1}, %2;" : "=f"(r.x), "=f"(r.y) : "l"(v)); return r;
}
__device__ __forceinline__ ull swp(ull v) {   // (x,y) -> (y,x)
    ull r;
    asm("{\n\t.reg .b32 lo, hi;\n\tmov.b64 {lo, hi}, %1;\n\tmov.b64 %0, {hi, lo};\n\t}"
        : "=l"(r) : "l"(v));
    return r;
}
__device__ __forceinline__ ull f2mul(ull a, ull b) {
    ull r; asm("mul.rn.f32x2 %0, %1, %2;" : "=l"(r) : "l"(a), "l"(b)); return r;
}
__device__ __forceinline__ ull f2fma(ull a, ull b, ull c) {
    ull r; asm("fma.rn.f32x2 %0, %1, %2, %3;" : "=l"(r) : "l"(a), "l"(b), "l"(c)); return r;
}
__device__ __forceinline__ void red2(float2* p, float2 v) {
    asm volatile("red.global.add.v2.f32 [%0], {%1, %2};"
                 :: "l"(p), "f"(v.x), "f"(v.y) : "memory");
}

// ---------------- gates (shared) ----------------
template<int RB>
__device__ __forceinline__ void gry(ull* r, float2 cs) {
    const ull c2 = dup2(cs.x), s2 = dup2(cs.y), ns2 = dup2(-cs.y);
#pragma unroll
    for (int j = 0; j < 16; ++j) {
        if (!(j & (1 << RB))) {
            ull a0 = r[j], a1 = r[j | (1 << RB)];
            r[j]            = f2fma(c2, a0, f2mul(ns2, a1));
            r[j | (1 << RB)] = f2fma(s2, a0, f2mul(c2, a1));
        }
    }
}
template<int RBC, int RBT>
__device__ __forceinline__ void gcrx(ull* r, float2 cs) {
    const ull c2 = dup2(cs.x);
    const ull spm = pk2(cs.y, -cs.y);
#pragma unroll
    for (int j = 0; j < 16; ++j) {
        if ((j & (1 << RBC)) && !(j & (1 << RBT))) {
            ull a0 = r[j], a1 = r[j | (1 << RBT)];
            r[j]             = f2fma(c2, a0, f2mul(spm, swp(a1)));
            r[j | (1 << RBT)] = f2fma(c2, a1, f2mul(spm, swp(a0)));
        }
    }
}

// ======================= circuit machinery (sw5 + warp-local runs) =========
// Fold swizzle: bank bits = i[0:4] ^ i[4:8] ^ i[8:12]
__device__ __forceinline__ uint32_t sw5(uint32_t i) {
    return i ^ ((i >> 4) & 0xFu) ^ ((i >> 8) & 0xFu);
}

// Window bits P0..P3 hold register amp bits; tid bits 0..7 deposit at D0..D7.
// D0..D3 (intra-half-warp lanes) chosen with distinct residues mod 4 -> sw5
// conflict-free. D5..D7 = F positions (warp id), shared within each run.
template<int P0,int P1,int P2,int P3,
         int D0,int D1,int D2,int D3,int D4,int D5,int D6,int D7>
struct P4 {
    static __device__ __forceinline__ uint32_t base(int tid) {
        return ((tid & 1)   ? (1u << D0) : 0u)
             | ((tid & 2)   ? (1u << D1) : 0u)
             | ((tid & 4)   ? (1u << D2) : 0u)
             | ((tid & 8)   ? (1u << D3) : 0u)
             | ((tid & 16)  ? (1u << D4) : 0u)
             | ((tid & 32)  ? (1u << D5) : 0u)
             | ((tid & 64)  ? (1u << D6) : 0u)
             | ((tid & 128) ? (1u << D7) : 0u);
    }
    static __device__ __forceinline__ uint32_t idx(uint32_t b, int j) {
        return b | ((j & 1) ? (1u << P0) : 0u)
                 | ((j & 2) ? (1u << P1) : 0u)
                 | ((j & 4) ? (1u << P2) : 0u)
                 | ((j & 8) ? (1u << P3) : 0u);
    }
};

// Runs: (A1,A2) F={8,9,10}; (A3,A4) F={0,1,2}; (B1,B2) F={2,3,4};
//       (B3,B4) F={8,9,10}. B4 -> next-layer A1 also warp-local (same F).
typedef P4<11,0,1,2,   3,4,5,6,7, 8,9,10>  QA1;
typedef P4<2,3,4,5,    0,1,6,7,11, 8,9,10> QA2;
typedef P4<5,6,7,8,    3,4,9,10,11, 0,1,2> QA3;
typedef P4<8,9,10,11,  3,4,5,6,7, 0,1,2>   QA4;
typedef P4<1,0,11,10,  5,6,7,8,9, 2,3,4>   QB1;
typedef P4<10,9,8,7,   0,1,6,11,5, 2,3,4>  QB2;
typedef P4<7,6,5,4,    0,1,2,3,11, 8,9,10> QB3;
typedef P4<4,3,2,1,    0,5,6,7,11, 8,9,10> QB4;

#define Q_LOAD(T)                                                          \
    uint32_t base = T::base(tid);                                          \
    ull r[16];                                                             \
    _Pragma("unroll")                                                      \
    for (int j = 0; j < 16; ++j) r[j] = st[sw5(T::idx(base, j))];

#define Q_STORE(T)                                                         \
    _Pragma("unroll")                                                      \
    for (int j = 0; j < 16; ++j) st[sw5(T::idx(base, j))] = r[j];

__device__ __forceinline__ void qA1_body(ull* r, const float2* c) {
    gry<0>(r, c[0]);  gry<1>(r, c[11]); gry<2>(r, c[10]); gry<3>(r, c[9]);
    gcrx<1, 0>(r, c[12]); gcrx<2, 1>(r, c[13]); gcrx<3, 2>(r, c[14]);
}
__device__ __forceinline__ void qA1(ull* st, const float2* c, int tid) {
    Q_LOAD(QA1);
    qA1_body(r, c);
    Q_STORE(QA1);
}
__device__ __forceinline__ void qA1_zero(ull* st, const float2* c, int tid) {
    uint32_t base = QA1::base(tid);
    ull r[16];
#pragma unroll
    for (int j = 0; j < 16; ++j) r[j] = 0ull;
    if (tid == 0) r[0] = pk2(1.f, 0.f);
    qA1_body(r, c);
    Q_STORE(QA1);
}
__device__ __forceinline__ void qA2(ull* st, const float2* c, int tid) {
    Q_LOAD(QA2);
    gry<1>(r, c[8]); gry<2>(r, c[7]); gry<3>(r, c[6]);
    gcrx<1, 0>(r, c[15]); gcrx<2, 1>(r, c[16]); gcrx<3, 2>(r, c[17]);
    Q_STORE(QA2);
}
__device__ __forceinline__ void qA3(ull* st, const float2* c, int tid) {
    Q_LOAD(QA3);
    gry<1>(r, c[5]); gry<2>(r, c[4]); gry<3>(r, c[3]);
    gcrx<1, 0>(r, c[18]); gcrx<2, 1>(r, c[19]); gcrx<3, 2>(r, c[20]);
    Q_STORE(QA3);
}
__device__ __forceinline__ void qA4(ull* st, const float2* c, int tid) {
    Q_LOAD(QA4);
    gry<1>(r, c[2]); gry<2>(r, c[1]);
    gcrx<1, 0>(r, c[21]); gcrx<2, 1>(r, c[22]); gcrx<3, 2>(r, c[23]);
    Q_STORE(QA4);
}
__device__ __forceinline__ void qB1(ull* st, const float2* c, int tid) {
    Q_LOAD(QB1);
    gry<0>(r, c[34]); gry<1>(r, c[35]); gry<2>(r, c[24]); gry<3>(r, c[25]);
    gcrx<1, 0>(r, c[36]); gcrx<2, 1>(r, c[37]); gcrx<3, 2>(r, c[38]);
    Q_STORE(QB1);
}
__device__ __forceinline__ void qB2(ull* st, const float2* c, int tid) {
    Q_LOAD(QB2);
    gry<1>(r, c[26]); gry<2>(r, c[27]); gry<3>(r, c[28]);
    gcrx<1, 0>(r, c[39]); gcrx<2, 1>(r, c[40]); gcrx<3, 2>(r, c[41]);
    Q_STORE(QB2);
}
__device__ __forceinline__ void qB3(ull* st, const float2* c, int tid) {
    Q_LOAD(QB3);
    gry<1>(r, c[29]); gry<2>(r, c[30]); gry<3>(r, c[31]);
    gcrx<1, 0>(r, c[42]); gcrx<2, 1>(r, c[43]); gcrx<3, 2>(r, c[44]);
    Q_STORE(QB3);
}
__device__ __forceinline__ void qB4(ull* st, const float2* c, int tid) {
    Q_LOAD(QB4);
    gry<1>(r, c[32]); gry<2>(r, c[33]);
    gcrx<1, 0>(r, c[45]); gcrx<2, 1>(r, c[46]); gcrx<3, 2>(r, c[47]);
    Q_STORE(QB4);
}

// ======================= 4-bit machinery for final_kernel (unchanged) ======
__device__ __forceinline__ uint32_t sw(uint32_t i) { return i ^ ((i >> 4) & 0xFu); }

template<int P0, int P1, int P2, int P3>
__device__ __forceinline__ uint32_t phase_base(int tid) {
    constexpr uint32_t M = (1u << P0) | (1u << P1) | (1u << P2) | (1u << P3);
    uint32_t base = 0;
    int tb = 0;
#pragma unroll
    for (int pos = 0; pos < NQ; ++pos) {
        if (!((M >> pos) & 1u)) {
            base |= ((uint32_t)(tid >> tb) & 1u) << pos;
            ++tb;
        }
    }
    return base;
}
template<int P0, int P1, int P2, int P3>
__device__ __forceinline__ uint32_t pidx(uint32_t base, int j) {
    return base
        | ((j & 1) ? (1u << P0) : 0u)
        | ((j & 2) ? (1u << P1) : 0u)
        | ((j & 4) ? (1u << P2) : 0u)
        | ((j & 8) ? (1u << P3) : 0u);
}

#define PHASE_LOAD(P0,P1,P2,P3)                                            \
    uint32_t base = phase_base<P0,P1,P2,P3>(tid);                          \
    ull r[16];                                                             \
    _Pragma("unroll")                                                      \
    for (int j = 0; j < 16; ++j) r[j] = st[sw(pidx<P0,P1,P2,P3>(base, j))];

#define PHASE_STORE(P0,P1,P2,P3)                                           \
    _Pragma("unroll")                                                      \
    for (int j = 0; j < 16; ++j) st[sw(pidx<P0,P1,P2,P3>(base, j))] = r[j];

__device__ __forceinline__ void phA1(ull* st, const float2* c, int tid) {
    PHASE_LOAD(11, 0, 1, 2);
    gry<0>(r, c[0]);  gry<1>(r, c[11]); gry<2>(r, c[10]); gry<3>(r, c[9]);
    gcrx<1, 0>(r, c[12]); gcrx<2, 1>(r, c[13]); gcrx<3, 2>(r, c[14]);
    PHASE_STORE(11, 0, 1, 2);
}
__device__ __forceinline__ void phA2(ull* st, const float2* c, int tid) {
    PHASE_LOAD(2, 3, 4, 5);
    gry<1>(r, c[8]); gry<2>(r, c[7]); gry<3>(r, c[6]);
    gcrx<1, 0>(r, c[15]); gcrx<2, 1>(r, c[16]); gcrx<3, 2>(r, c[17]);
    PHASE_STORE(2, 3, 4, 5);
}
__device__ __forceinline__ void phA3(ull* st, const float2* c, int tid) {
    PHASE_LOAD(5, 6, 7, 8);
    gry<1>(r, c[5]); gry<2>(r, c[4]); gry<3>(r, c[3]);
    gcrx<1, 0>(r, c[18]); gcrx<2, 1>(r, c[19]); gcrx<3, 2>(r, c[20]);
    PHASE_STORE(5, 6, 7, 8);
}
__device__ __forceinline__ void phA4(ull* st, const float2* c, int tid) {
    PHASE_LOAD(8, 9, 10, 11);
    gry<1>(r, c[2]); gry<2>(r, c[1]);
    gcrx<1, 0>(r, c[21]); gcrx<2, 1>(r, c[22]); gcrx<3, 2>(r, c[23]);
    PHASE_STORE(8, 9, 10, 11);
}
__device__ __forceinline__ void phB1(ull* st, const float2* c, int tid) {
    PHASE_LOAD(1, 0, 11, 10);
    gry<0>(r, c[34]); gry<1>(r, c[35]); gry<2>(r, c[24]); gry<3>(r, c[25]);
    gcrx<1, 0>(r, c[36]); gcrx<2, 1>(r, c[37]); gcrx<3, 2>(r, c[38]);
    PHASE_STORE(1, 0, 11, 10);
}
__device__ __forceinline__ void phB2(ull* st, const float2* c, int tid) {
    PHASE_LOAD(10, 9, 8, 7);
    gry<1>(r, c[26]); gry<2>(r, c[27]); gry<3>(r, c[28]);
    gcrx<1, 0>(r, c[39]); gcrx<2, 1>(r, c[40]); gcrx<3, 2>(r, c[41]);
    PHASE_STORE(10, 9, 8, 7);
}
__device__ __forceinline__ void phB3(ull* st, const float2* c, int tid) {
    PHASE_LOAD(7, 6, 5, 4);
    gry<1>(r, c[29]); gry<2>(r, c[30]); gry<3>(r, c[31]);
    gcrx<1, 0>(r, c[42]); gcrx<2, 1>(r, c[43]); gcrx<3, 2>(r, c[44]);
    PHASE_STORE(7, 6, 5, 4);
}
__device__ __forceinline__ void phB4(ull* st, const float2* c, int tid) {
    PHASE_LOAD(4, 3, 2, 1);
    gry<1>(r, c[32]); gry<2>(r, c[33]);
    gcrx<1, 0>(r, c[45]); gcrx<2, 1>(r, c[46]); gcrx<3, 2>(r, c[47]);
    PHASE_STORE(4, 3, 2, 1);
}
__device__ __forceinline__ void run_layer(ull* st, const float2* c, int tid) {
    phA1(st, c, tid); __syncthreads();
    phA2(st, c, tid); __syncthreads();
    phA3(st, c, tid); __syncthreads();
    phA4(st, c, tid); __syncthreads();
    phB1(st, c, tid); __syncthreads();
    phB2(st, c, tid); __syncthreads();
    phB3(st, c, tid); __syncthreads();
    phB4(st, c, tid); __syncthreads();
}

// ---------------------------------------------------------------------------
// Kernel 1: prep = zero g_work[1..4] (+ queue reset in block 0).
// ---------------------------------------------------------------------------
#define INIT_BLKS 512
__global__ void prep_kernel() {
    if (blockIdx.x == 0) {
        if (threadIdx.x == 0) g_ticket = 0u;
        if (threadIdx.x < DEGREE * BATCH) g_done[threadIdx.x] = 0u;
    }
    uint32_t tgid = blockIdx.x * 256 + threadIdx.x;     // 0..131071
    float4* p = (float4*)&g_work[0][0] + 131072 + (size_t)tgid * 4;
    float4 z = make_float4(0.f, 0.f, 0.f, 0.f);
    p[0] = z; p[1] = z; p[2] = z; p[3] = z;
}

// ---------------------------------------------------------------------------
// Kernel 2: persistent fused circuits. 592 CTAs, ticket queue over (d,b,t).
// Intra-run phase boundaries are __syncwarp (warp-local data flow).
// ---------------------------------------------------------------------------
__global__ void __launch_bounds__(256, 4)
circuit_fused(const float* __restrict__ x,
              const float* __restrict__ Wp,
              const float* __restrict__ bp,
              const float* __restrict__ mix_re,
              const float* __restrict__ mix_im) {
    extern __shared__ ull dsm[];
    ull* st = dsm;                            // DIM
    float2* cc = (float2*)(dsm + DIM);        // 96 coeffs + mix at [96]
    __shared__ unsigned s_ticket;

    const int tid = threadIdx.x;
    unsigned prev_slot = 0xFFFFFFFFu;         // no completed item yet

    for (;;) {
        __syncthreads();                      // all threads done with prev item
        if (tid == 0) {
            if (prev_slot != 0xFFFFFFFFu)
                asm volatile("red.release.gpu.global.add.u32 [%0], 1;"
                             :: "l"(&g_done[prev_slot]) : "memory");
            s_ticket = atomicAdd(&g_ticket, 1u);
        }
        __syncthreads();
        const unsigned item = s_ticket;
        if (item >= NITEMS) break;
        const unsigned slot = item >> 5;      // d*64 + b
        const int b = slot & 63;
        const int t = item & 31;
        const int d = slot >> 6;
        const int bt = b * TSTEPS + t;

        if (d == 0) {
            // compute this (b,t)'s rotation params in-item
            float4* xr = (float4*)st;         // reuse st head as x staging
            if (tid < FDIM / 4) xr[tid] = ((const float4*)(x + bt * FDIM))[tid];
            __syncthreads();
            if (tid < NROTS) {
                const float4* wrow = (const float4*)(Wp + tid * FDIM);
                float acc = bp[tid];
#pragma unroll
                for (int f = 0; f < FDIM / 4; ++f) {
                    float4 xv = xr[f], wv = wrow[f];
                    acc += xv.x * wv.x + xv.y * wv.y + xv.z * wv.z + xv.w * wv.w;
                }
                float sg = 1.0f / (1.0f + __expf(-acc));
                float h = 3.14159265358979323846f * sg;
                float sv, cv; __sincosf(h, &sv, &cv);
                float2 cs_ = make_float2(cv, sv);
                cc[tid] = cs_;
                g_cs[bt * NROTS + tid] = cs_;   // publish for d>0 consumers
            }
            if (tid == NROTS) cc[NROTS] = make_float2(mix_re[t], mix_im[t]);
            __syncthreads();
            qA1_zero(st, cc, tid); __syncwarp();       // analytic |0..0> start
        } else {
            // wait for the 32 producers of work[d] for this b
            if (tid == 0) {
                unsigned v;
                for (;;) {
                    asm volatile("ld.acquire.gpu.global.u32 %0, [%1];"
                                 : "=r"(v) : "l"(&g_done[slot - 64]) : "memory");
                    if (v >= (unsigned)TSTEPS) break;
                    __nanosleep(64);
                }
            }
            __syncthreads();                  // broadcast acquire to CTA

            const ull* win = (const ull*)&g_work[d][b * DIM];
#pragma unroll
            for (int k = 0; k < 16; ++k) {
                int i = tid + 256 * k;
                st[sw5((uint32_t)i)] = win[i];
            }
            if (tid < NROTS) cc[tid] = g_cs[bt * NROTS + tid];
            if (tid == NROTS) cc[NROTS] = make_float2(mix_re[t], mix_im[t]);
            __syncthreads();
            qA1(st, cc, tid); __syncwarp();
        }

        // layer 0 remainder: warp-sync within runs, full sync between runs
        qA2(st, cc, tid); __syncthreads();
        qA3(st, cc, tid); __syncwarp();
        qA4(st, cc, tid); __syncthreads();
        qB1(st, cc, tid); __syncwarp();
        qB2(st, cc, tid); __syncthreads();
        qB3(st, cc, tid); __syncwarp();
        qB4(st, cc, tid); __syncwarp();       // B4 -> A1 shares F = {8,9,10}
        // layer 1
        const float2* c1 = cc + 48;
        qA1(st, c1, tid); __syncwarp();
        qA2(st, c1, tid); __syncthreads();
        qA3(st, c1, tid); __syncwarp();
        qA4(st, c1, tid); __syncthreads();
        qB1(st, c1, tid); __syncwarp();
        qB2(st, c1, tid); __syncthreads();
        qB3(st, c1, tid); __syncwarp();
        {   // qB4 without store: mix[t] * psi -> red.global directly
            float2* wout = &g_work[d + 1][b * DIM];
            Q_LOAD(QB4);
            gry<1>(r, c1[32]); gry<2>(r, c1[33]);
            gcrx<1, 0>(r, c1[45]); gcrx<2, 1>(r, c1[46]); gcrx<3, 2>(r, c1[47]);
            float2 mx = cc[NROTS];
            const ull mr2 = dup2(mx.x);
            const ull mpm = pk2(-mx.y, mx.y);
#pragma unroll
            for (int j = 0; j < 16; ++j) {
                uint32_t i = QB4::idx(base, j);
                ull v = f2fma(mr2, r[j], f2mul(mpm, swp(r[j])));
                red2(&wout[i], upk(v));
            }
        }
        prev_slot = slot;                     // signal at next loop top
    }
}

// ---------------------------------------------------------------------------
// Kernel 3: analytic p[0] + assemble, normalize, qff layer, Pauli expvals,
// output linear. grid = 64, 256 threads (4-bit machinery, old sw).
// ---------------------------------------------------------------------------
__global__ void final_kernel(const float* __restrict__ poly,
                             const float* __restrict__ qff,
                             const float* __restrict__ W_out,
                             const float* __restrict__ b_out,
                             float* __restrict__ out) {
    __shared__ ull st[DIM];
    __shared__ float red[37];            // [0..35] expvals, [36] sumsq
    __shared__ float2 csqff[QFFROTS];
    const int tid = threadIdx.x;
    const int b = blockIdx.x;

    if (tid < QFFROTS) {
        float hq = 0.5f * qff[tid];
        float sq, cq; __sincosf(hq, &sq, &cq);
        csqff[tid] = make_float2(cq, sq);
    }

    float p[DEGREE + 1];
#pragma unroll
    for (int d = 0; d <= DEGREE; ++d) p[d] = poly[d];
    float sabs = 0.f;
#pragma unroll
    for (int d = 0; d <= DEGREE; ++d) sabs += fabsf(p[d]);
    const float inv_s = 1.f / sabs;

    if (tid == 0) red[36] = 0.f;
    const ull* wflat = (const ull*)&g_work[0][0];
    float lsq = 0.f;
#pragma unroll
    for (int k = 0; k < 16; ++k) {
        int i = tid + 256 * k;
        ull v = 0ull;
#pragma unroll
        for (int d = 1; d <= DEGREE; ++d) {
            ull w = wflat[(size_t)d * (BATCH * DIM) + b * DIM + i];
            v = f2fma(dup2(p[d]), w, v);
        }
        if (i == 0) v = f2fma(dup2(p[0]), pk2(1.f, 0.f), v);  // analytic base
        v = f2mul(dup2(inv_s), v);
        st[sw((uint32_t)i)] = v;
        float2 vf = upk(v);
        lsq += vf.x * vf.x + vf.y * vf.y;
    }
#pragma unroll
    for (int o = 16; o > 0; o >>= 1) lsq += __shfl_xor_sync(0xffffffffu, lsq, o);
    if ((tid & 31) == 0) atomicAdd(&red[36], lsq);
    __syncthreads();

    const float f = 1.f / (sqrtf(red[36]) + 1e-9f);
    const ull f2 = dup2(f);
#pragma unroll
    for (int k = 0; k < 16; ++k) {
        int i = tid + 256 * k;
        uint32_t s_ = sw((uint32_t)i);
        st[s_] = f2mul(f2, st[s_]);
    }
    __syncthreads();

    run_layer(st, csqff, tid);       // qff: one sim14 layer

    if (tid < 36) red[tid] = 0.f;
    __syncthreads();

    float xx[NQ], yy[NQ], zz[NQ];
#pragma unroll
    for (int w = 0; w < NQ; ++w) { xx[w] = 0.f; yy[w] = 0.f; zz[w] = 0.f; }

#pragma unroll
    for (int k = 0; k < 16; ++k) {
        int i = tid + 256 * k;
        float2 a = upk(st[sw((uint32_t)i)]);
        float n2 = a.x * a.x + a.y * a.y;
#pragma unroll
        for (int w = 0; w < NQ; ++w) {
            int pbit = 11 - w;
            if (((i >> pbit) & 1) == 0) {
                float2 a1 = upk(st[sw((uint32_t)(i | (1 << pbit)))]);
                xx[w] += 2.f * (a.x * a1.x + a.y * a1.y);
                yy[w] += 2.f * (a.x * a1.y - a.y * a1.x);
                zz[w] += n2;
            } else {
                zz[w] -= n2;
            }
        }
    }
#pragma unroll
    for (int w = 0; w < NQ; ++w) {
        atomicAdd(&red[w], xx[w]);
        atomicAdd(&red[12 + w], yy[w]);
        atomicAdd(&red[24 + w], zz[w]);
    }
    __syncthreads();

    if (tid < ODIM) {
        float acc = b_out[tid];
#pragma unroll
        for (int j = 0; j < 36; ++j) acc += W_out[tid * 36 + j] * red[j];
        out[b * ODIM + tid] = acc;
    }
}

// ---------------------------------------------------------------------------
// Inputs (metadata order): x, W_proj, b_proj, poly_coeffs, mix_re, mix_im,
//                          qff_params, W_out, b_out.  Output: float32 [64,8].
// ---------------------------------------------------------------------------
extern "C" void kernel_launch(void* const* d_in, const int* in_sizes, int n_in,
                              void* d_out, int out_size) {
    (void)in_sizes; (void)n_in; (void)out_size;
    const float* x      = (const float*)d_in[0];
    const float* W_proj = (const float*)d_in[1];
    const float* b_proj = (const float*)d_in[2];
    const float* poly   = (const float*)d_in[3];
    const float* mix_re = (const float*)d_in[4];
    const float* mix_im = (const float*)d_in[5];
    const float* qff    = (const float*)d_in[6];
    const float* W_out  = (const float*)d_in[7];
    const float* b_out  = (const float*)d_in[8];
    float* out = (float*)d_out;

    cudaFuncSetAttribute(circuit_fused,
                         cudaFuncAttributeMaxDynamicSharedMemorySize, CIRC_SMEM);

    prep_kernel<<<INIT_BLKS, 256>>>();
    circuit_fused<<<NPERS, 256, CIRC_SMEM>>>(x, W_proj, b_proj, mix_re, mix_im);
    final_kernel<<<BATCH, 256>>>(poly, qff, W_out, b_out, out);
}